// round 6
// baseline (speedup 1.0000x reference)
#include <cuda_runtime.h>
#include <cuda_fp16.h>
#include <cstdint>

// Problem constants
static constexpr int N_CELL  = 50000;
static constexpr int N_NET   = 10000;
static constexpr int N_GCELL = 20000;
static constexpr int E       = 100000;
static constexpr int D       = 32;
static constexpr int N_PTOT  = N_NET + N_GCELL;                    // 30000 P rows

// Degree-counter layout
static constexpr int OFF_PINS_S   = 0;
static constexpr int OFF_PINS_D   = OFF_PINS_S + N_CELL;
static constexpr int OFF_CON_S    = OFF_PINS_D + N_NET;
static constexpr int OFF_CON_D    = OFF_CON_S + N_GCELL;
static constexpr int OFF_PT_S     = OFF_CON_D + N_GCELL;
static constexpr int OFF_PT_D     = OFF_PT_S + N_CELL;
static constexpr int OFF_PINNED_D = OFF_PT_D + N_GCELL;
static constexpr int OFF_PF_D     = OFF_PINNED_D + N_CELL;
static constexpr int DEG_TOTAL    = OFF_PF_D + N_CELL;             // 270000

// Scratch
__device__ int    g_deg[DEG_TOTAL];
__device__ float  g_feat_pins[N_CELL * D];
__device__ float  g_feat_pt[N_CELL * D];
__device__ float  g_feat_connect[N_GCELL * D];
__device__ __align__(16) __half g_P[(size_t)N_PTOT * 544];   // fp16 NNConv factor

// ---------------------------------------------------------------------------
// f32x2 packed-FMA helpers (Blackwell FFMA2)
typedef unsigned long long ull;
__device__ __forceinline__ ull f2pack(float lo, float hi) {
    ull r; asm("mov.b64 %0, {%1,%2};" : "=l"(r) : "f"(lo), "f"(hi)); return r;
}
__device__ __forceinline__ void f2unpack(ull v, float& lo, float& hi) {
    asm("mov.b64 {%0,%1}, %2;" : "=f"(lo), "=f"(hi) : "l"(v));
}
__device__ __forceinline__ ull ffma2(ull a, ull b, ull c) {
    ull d; asm("fma.rn.f32x2 %0, %1, %2, %3;" : "=l"(d) : "l"(a), "l"(b), "l"(c)); return d;
}

// No "memory" clobber: nothing in-kernel reads the red target; lets the
// compiler hoist independent gathers above earlier reductions.
__device__ __forceinline__ void red_add_v4(float* addr, float x, float y, float z, float w) {
    asm volatile("red.global.add.v4.f32 [%0], {%1,%2,%3,%4};"
                 :: "l"(addr), "f"(x), "f"(y), "f"(z), "f"(w));
}

// 8 halves (16B) -> 4 packed f32x2
struct F8 { ull v[4]; };
__device__ __forceinline__ F8 ldh8(const __half* p) {
    uint4 u = __ldg(reinterpret_cast<const uint4*>(p));
    unsigned uu[4] = {u.x, u.y, u.z, u.w};
    F8 r;
#pragma unroll
    for (int i = 0; i < 4; i++) {
        __half2 h = *reinterpret_cast<__half2*>(&uu[i]);
        float2 f = __half22float2(h);
        r.v[i] = f2pack(f.x, f.y);
    }
    return r;
}

// ---------------------------------------------------------------------------
// K1: zero degree counters + bias-init cell & gcell output regions (vectorized x4).
// out_net region is fully overwritten by the dense kernel.
static constexpr int INIT_V4    = ((N_CELL + N_GCELL) * D) / 4;   // 560000
static constexpr int DEG_V4     = (DEG_TOTAL + 3) / 4;            // 67500
__global__ void init_kernel(float* __restrict__ out,
                            const float* __restrict__ b_pinned,
                            const float* __restrict__ b_pf,
                            const float* __restrict__ b_connect,
                            const float* __restrict__ b_pt) {
    int idx = blockIdx.x * blockDim.x + threadIdx.x;
    if (idx < DEG_V4) {
        // DEG_TOTAL = 270000 is divisible by 4? 270000/4 = 67500 exactly.
        *reinterpret_cast<int4*>(&g_deg[idx * 4]) = make_int4(0, 0, 0, 0);
    }
    if (idx >= INIT_V4) return;
    int elem = idx * 4;
    int row = elem >> 5;
    int j = elem & 31;          // 0,4,8,...,28
    float4 v;
    if (row < N_CELL) {
        v = make_float4(b_pinned[j] + b_pf[j],         b_pinned[j+1] + b_pf[j+1],
                        b_pinned[j+2] + b_pf[j+2],     b_pinned[j+3] + b_pf[j+3]);
        *reinterpret_cast<float4*>(&out[elem]) = v;
    } else {
        v = make_float4(b_connect[j] + b_pt[j],        b_connect[j+1] + b_pt[j+1],
                        b_connect[j+2] + b_pt[j+2],    b_connect[j+3] + b_pt[j+3]);
        *reinterpret_cast<float4*>(&out[(size_t)(row + N_NET) * 32 + j]) = v;
    }
}

// ---------------------------------------------------------------------------
// K2: degree counting for all 8 (index, n) pairs
__global__ void degree_kernel(const int* __restrict__ pins_src, const int* __restrict__ pins_dst,
                              const int* __restrict__ connect_src, const int* __restrict__ connect_dst,
                              const int* __restrict__ pt_src, const int* __restrict__ pt_dst,
                              const int* __restrict__ pinned_dst, const int* __restrict__ pf_dst) {
    int e = blockIdx.x * blockDim.x + threadIdx.x;
    if (e >= E) return;
    atomicAdd(&g_deg[OFF_PINS_S   + pins_src[e]], 1);
    atomicAdd(&g_deg[OFF_PINS_D   + pins_dst[e]], 1);
    atomicAdd(&g_deg[OFF_CON_S    + connect_src[e]], 1);
    atomicAdd(&g_deg[OFF_CON_D    + connect_dst[e]], 1);
    atomicAdd(&g_deg[OFF_PT_S     + pt_src[e]], 1);
    atomicAdd(&g_deg[OFF_PT_D     + pt_dst[e]], 1);
    atomicAdd(&g_deg[OFF_PINNED_D + pinned_dst[e]], 1);
    atomicAdd(&g_deg[OFF_PF_D     + pf_dst[e]], 1);
}

// ---------------------------------------------------------------------------
// K3: all dense GEMMs (f32x2). Src-side GraphConv norm applied in the epilogue.
static constexpr int NT_P    = (N_PTOT + 31) / 32;     // 938
static constexpr int NB_P    = NT_P * 5;               // 4690
static constexpr int NT_DUAL = (N_CELL + 31) / 32;     // 1563
static constexpr int NT_CON  = (N_GCELL + 31) / 32;    // 625
static constexpr int NT_NET  = (N_NET + 31) / 32;      // 313
static constexpr int NB_DENSE = NB_P + NT_DUAL + NT_CON + NT_NET;

__global__ __launch_bounds__(256) void dense_kernel(
        const float* __restrict__ node_feat,
        const float* __restrict__ net_feat,
        const float* __restrict__ hanna_feat,
        const float* __restrict__ W_topo, const float* __restrict__ b_topo,
        const float* __restrict__ W_pins, const float* __restrict__ W_pt,
        const float* __restrict__ W_connect, const float* __restrict__ W_net,
        const float* __restrict__ b_pins, const float* __restrict__ b_net,
        float* __restrict__ out_net) {
    __shared__ ull Asm2[32 * 33];    // (a,a) packed A tile
    __shared__ ull Wsm2[32 * 64];    // paired W columns

    int bid = blockIdx.x;
    int tid = threadIdx.x;

    int jobtype, tile, grp = 0;
    if (bid < NB_P)                        { jobtype = 0; tile = bid / 5; grp = bid % 5; }
    else if (bid < NB_P + NT_DUAL)         { jobtype = 1; tile = bid - NB_P; }
    else if (bid < NB_P + NT_DUAL + NT_CON){ jobtype = 2; tile = bid - NB_P - NT_DUAL; }
    else                                   { jobtype = 3; tile = bid - NB_P - NT_DUAL - NT_CON; }

    int n0 = tile * 32;
    int nrows = (jobtype == 0) ? N_PTOT : (jobtype == 1) ? N_CELL : (jobtype == 2) ? N_GCELL : N_NET;

    // ---- stage A (packed (a,a)) ----
    for (int idx = tid; idx < 32 * 32; idx += 256) {
        int r = idx >> 5, c = idx & 31;
        int node = n0 + r;
        float v = 0.0f;
        if (node < nrows) {
            if (jobtype == 0)      v = (node < N_NET) ? net_feat[node * 32 + c]
                                                      : hanna_feat[(node - N_NET) * 32 + c];
            else if (jobtype == 1) v = node_feat[node * 32 + c];
            else if (jobtype == 2) v = hanna_feat[node * 32 + c];
            else                   v = net_feat[node * 32 + c];
        }
        Asm2[r * 33 + c] = f2pack(v, v);
    }

    // ---- stage W pairs ----
    int npairs = (jobtype == 0) ? ((grp < 4) ? 64 : 16) : (jobtype == 1) ? 32 : 16;
    for (int idx = tid; idx < 32 * npairs; idx += 256) {
        int i = idx / npairs, p = idx % npairs;
        float2 w;
        if (jobtype == 0) {
            if (grp < 4) {
                int slot = grp * 4 + (p >> 4);
                w = *(const float2*)&W_topo[slot * 1024 + i * 32 + (p & 15) * 2];
            } else {
                w = *(const float2*)&b_topo[i * 32 + p * 2];
            }
        } else if (jobtype == 1) {
            w = (p < 16) ? *(const float2*)&W_pins[i * 32 + p * 2]
                         : *(const float2*)&W_pt[i * 32 + (p - 16) * 2];
        } else if (jobtype == 2) {
            w = *(const float2*)&W_connect[i * 32 + p * 2];
        } else {
            w = *(const float2*)&W_net[i * 32 + p * 2];
        }
        Wsm2[i * npairs + p] = f2pack(w.x, w.y);
    }
    __syncthreads();

    // ---- compute + store ----
    if (jobtype == 0 && grp < 4) {
        int tx = tid & 31, ty = tid >> 5;
        ull acc[4][2] = {};
#pragma unroll
        for (int i = 0; i < 32; i++) {
            ull w0 = Wsm2[i * 64 + tx];
            ull w1 = Wsm2[i * 64 + 32 + tx];
#pragma unroll
            for (int r = 0; r < 4; r++) {
                ull a = Asm2[(ty * 4 + r) * 33 + i];
                acc[r][0] = ffma2(a, w0, acc[r][0]);
                acc[r][1] = ffma2(a, w1, acc[r][1]);
            }
        }
#pragma unroll
        for (int r = 0; r < 4; r++) {
            int node = n0 + ty * 4 + r;
            if (node >= N_PTOT) break;
            float lo, hi;
            f2unpack(acc[r][0], lo, hi);
            *(__half2*)&g_P[(size_t)node * 544 + grp * 128 + tx * 2] = __floats2half2_rn(lo, hi);
            f2unpack(acc[r][1], lo, hi);
            *(__half2*)&g_P[(size_t)node * 544 + grp * 128 + 64 + tx * 2] = __floats2half2_rn(lo, hi);
        }
    } else if (jobtype == 1) {
        int tx = tid & 31, ty = tid >> 5;
        ull acc[4] = {};
#pragma unroll
        for (int i = 0; i < 32; i++) {
            ull w = Wsm2[i * 32 + tx];
#pragma unroll
            for (int r = 0; r < 4; r++)
                acc[r] = ffma2(Asm2[(ty * 4 + r) * 33 + i], w, acc[r]);
        }
#pragma unroll
        for (int r = 0; r < 4; r++) {
            int node = n0 + ty * 4 + r;
            if (node >= N_CELL) break;
            float lo, hi;
            f2unpack(acc[r], lo, hi);
            if (tx < 16) {
                float s = rsqrtf((float)max(g_deg[OFF_PINS_S + node], 1));
                *(float2*)&g_feat_pins[node * 32 + tx * 2] = make_float2(lo * s, hi * s);
            } else {
                float s = rsqrtf((float)max(g_deg[OFF_PT_S + node], 1));
                *(float2*)&g_feat_pt[node * 32 + (tx - 16) * 2] = make_float2(lo * s, hi * s);
            }
        }
    } else {
        int tx = tid & 15, tyy = tid >> 4;
        ull acc[2] = {};
#pragma unroll
        for (int i = 0; i < 32; i++) {
            ull w = Wsm2[i * 16 + tx];
            acc[0] = ffma2(Asm2[(tyy * 2 + 0) * 33 + i], w, acc[0]);
            acc[1] = ffma2(Asm2[(tyy * 2 + 1) * 33 + i], w, acc[1]);
        }
#pragma unroll
        for (int r = 0; r < 2; r++) {
            int node = n0 + tyy * 2 + r;
            if (node >= nrows) break;
            float lo, hi;
            f2unpack(acc[r], lo, hi);
            if (jobtype == 0) {
                *(__half2*)&g_P[(size_t)node * 544 + 512 + tx * 2] = __floats2half2_rn(lo, hi);
            } else if (jobtype == 2) {
                float s = rsqrtf((float)max(g_deg[OFF_CON_S + node], 1));
                *(float2*)&g_feat_connect[node * 32 + tx * 2] = make_float2(lo * s, hi * s);
            } else {
                float2 bb = make_float2(b_pins[tx * 2] + b_net[tx * 2],
                                        b_pins[tx * 2 + 1] + b_net[tx * 2 + 1]);
                *(float2*)&out_net[node * 32 + tx * 2] = make_float2(lo + bb.x, hi + bb.y);
            }
        }
    }
}

// ---------------------------------------------------------------------------
// K4: all 5 edge relations, 4 edges/warp (8 lanes/edge).
// GraphConv: out[dst] += feat[src] * rsqrt(deg_dst)  (src norm already in feat)
// NNConv:    16B P loads; lanes q<4 accumulate even k (incl bias), q>=4 odd k.
__global__ __launch_bounds__(256) void edge_kernel(
        const int* __restrict__ pins_src, const int* __restrict__ pins_dst,
        const int* __restrict__ con_src,  const int* __restrict__ con_dst,
        const int* __restrict__ pt_src,   const int* __restrict__ pt_dst,
        const int* __restrict__ pinned_src, const int* __restrict__ pinned_dst,
        const int* __restrict__ pf_src,   const int* __restrict__ pf_dst,
        const float* __restrict__ pin_feat, const float* __restrict__ edge_feat,
        float* __restrict__ out_cell, float* __restrict__ out_net, float* __restrict__ out_gcell) {
    int t = blockIdx.x * blockDim.x + threadIdx.x;
    int lane = t & 31;
    int e = ((t >> 5) << 2) + (lane >> 3);     // 4 edges per warp
    if (e >= E) return;
    int q = lane & 7;
    int baseLane = lane & 24;
    int g = q >> 2;          // 0: even k (+bias), 1: odd k
    int c4 = q & 3;          // 8-col chunk

    // ---- indices + degrees up front (max MLP) ----
    int s1 = pins_src[e],   d1 = pins_dst[e];
    int s2 = con_src[e],    d2 = con_dst[e];
    int s3 = pt_src[e],     d3 = pt_dst[e];
    int sA = pinned_src[e], dA = pinned_dst[e];
    int sB = pf_src[e] + N_NET, dB = pf_dst[e];

    float sc1 = rsqrtf((float)max(__ldg(&g_deg[OFF_PINS_D + d1]), 1));
    float sc2 = rsqrtf((float)max(__ldg(&g_deg[OFF_CON_D + d2]), 1));
    float sc3 = rsqrtf((float)max(__ldg(&g_deg[OFF_PT_D + d3]), 1));
    float invA = 1.0f / (float)max(__ldg(&g_deg[OFF_PINNED_D + dA]), 1);
    float invB = 1.0f / (float)max(__ldg(&g_deg[OFF_PF_D + dB]), 1);

    float evA0 = pin_feat[e * 16 + q],  evA1 = pin_feat[e * 16 + 8 + q];
    float evB0 = edge_feat[e * 16 + q], evB1 = edge_feat[e * 16 + 8 + q];

    // ---- GraphConv gathers ----
    float4 v1 = *reinterpret_cast<const float4*>(&g_feat_pins[s1 * 32 + q * 4]);
    float4 v2 = *reinterpret_cast<const float4*>(&g_feat_connect[s2 * 32 + q * 4]);
    float4 v3 = *reinterpret_cast<const float4*>(&g_feat_pt[s3 * 32 + q * 4]);

    // ---- NNConv accumulation (ffma2, 16B loads) ----
    const __half* PA = g_P + (size_t)sA * 544;
    const __half* PB = g_P + (size_t)sB * 544;

    F8 accA, accB;
    if (g == 0) { accA = ldh8(PA + 512 + c4 * 8); accB = ldh8(PB + 512 + c4 * 8); }
    else {
#pragma unroll
        for (int i = 0; i < 4; i++) { accA.v[i] = 0ull; accB.v[i] = 0ull; }
    }

#pragma unroll
    for (int kk = 0; kk < 8; kk++) {
        int k = kk * 2 + g;
        float cA = __shfl_sync(0xffffffffu, (kk < 4) ? evA0 : evA1, baseLane + (k & 7));
        float cB = __shfl_sync(0xffffffffu, (kk < 4) ? evB0 : evB1, baseLane + (k & 7));
        ull ccA = f2pack(cA, cA);
        ull ccB = f2pack(cB, cB);
        F8 pa = ldh8(PA + k * 32 + c4 * 8);
        F8 pb = ldh8(PB + k * 32 + c4 * 8);
#pragma unroll
        for (int i = 0; i < 4; i++) {
            accA.v[i] = ffma2(pa.v[i], ccA, accA.v[i]);
            accB.v[i] = ffma2(pb.v[i], ccB, accB.v[i]);
        }
    }

    // ---- all reductions at the end ----
    red_add_v4(out_net   + d1 * 32 + q * 4, v1.x * sc1, v1.y * sc1, v1.z * sc1, v1.w * sc1);
    red_add_v4(out_gcell + d2 * 32 + q * 4, v2.x * sc2, v2.y * sc2, v2.z * sc2, v2.w * sc2);
    red_add_v4(out_gcell + d3 * 32 + q * 4, v3.x * sc3, v3.y * sc3, v3.z * sc3, v3.w * sc3);

    float a0, a1, a2, a3, a4, a5, a6, a7;
    f2unpack(accA.v[0], a0, a1); f2unpack(accA.v[1], a2, a3);
    f2unpack(accA.v[2], a4, a5); f2unpack(accA.v[3], a6, a7);
    red_add_v4(out_cell + dA * 32 + c4 * 8,     a0 * invA, a1 * invA, a2 * invA, a3 * invA);
    red_add_v4(out_cell + dA * 32 + c4 * 8 + 4, a4 * invA, a5 * invA, a6 * invA, a7 * invA);

    f2unpack(accB.v[0], a0, a1); f2unpack(accB.v[1], a2, a3);
    f2unpack(accB.v[2], a4, a5); f2unpack(accB.v[3], a6, a7);
    red_add_v4(out_cell + dB * 32 + c4 * 8,     a0 * invB, a1 * invB, a2 * invB, a3 * invB);
    red_add_v4(out_cell + dB * 32 + c4 * 8 + 4, a4 * invB, a5 * invB, a6 * invB, a7 * invB);
}

// ---------------------------------------------------------------------------
extern "C" void kernel_launch(void* const* d_in, const int* in_sizes, int n_in,
                              void* d_out, int out_size) {
    const float* node_feat   = (const float*)d_in[0];
    const float* net_feat    = (const float*)d_in[1];
    const float* pin_feat    = (const float*)d_in[2];
    const float* hanna_feat  = (const float*)d_in[3];
    const float* edge_feat   = (const float*)d_in[4];
    const int*   pins_src    = (const int*)d_in[5];
    const int*   pins_dst    = (const int*)d_in[6];
    const int*   pinned_src  = (const int*)d_in[7];
    const int*   pinned_dst  = (const int*)d_in[8];
    const int*   connect_src = (const int*)d_in[9];
    const int*   connect_dst = (const int*)d_in[10];
    const int*   pt_src      = (const int*)d_in[11];
    const int*   pt_dst      = (const int*)d_in[12];
    const int*   pf_src      = (const int*)d_in[13];
    const int*   pf_dst      = (const int*)d_in[14];
    const float* W_net       = (const float*)d_in[15];
    const float* b_net       = (const float*)d_in[16];
    const float* W_topo      = (const float*)d_in[17];
    const float* b_topo      = (const float*)d_in[18];
    const float* W_pins      = (const float*)d_in[19];
    const float* b_pins      = (const float*)d_in[20];
    const float* W_connect   = (const float*)d_in[21];
    const float* b_connect   = (const float*)d_in[22];
    const float* W_pt        = (const float*)d_in[23];
    const float* b_pt        = (const float*)d_in[24];
    const float* b_pinned    = (const float*)d_in[25];
    const float* b_pf        = (const float*)d_in[26];

    float* out       = (float*)d_out;
    float* out_net   = out + (size_t)N_CELL * D;
    float* out_gcell = out + (size_t)(N_CELL + N_NET) * D;

    // K1: zero degrees + bias-init cell/gcell output regions (vectorized)
    init_kernel<<<(INIT_V4 + 255) / 256, 256>>>(out, b_pinned, b_pf, b_connect, b_pt);

    // K2: degrees
    degree_kernel<<<(E + 255) / 256, 256>>>(pins_src, pins_dst, connect_src, connect_dst,
                                            pt_src, pt_dst, pinned_dst, pf_dst);

    // K3: all dense GEMMs (src norm folded into epilogue)
    dense_kernel<<<NB_DENSE, 256>>>(node_feat, net_feat, hanna_feat,
                                    W_topo, b_topo, W_pins, W_pt, W_connect, W_net,
                                    b_pins, b_net, out_net);

    // K4: all 5 edge relations
    const int EGRID = (E / 4 * 32 + 255) / 256;   // 3125 blocks
    edge_kernel<<<EGRID, 256>>>(pins_src, pins_dst, connect_src, connect_dst,
                                pt_src, pt_dst, pinned_src, pinned_dst, pf_src, pf_dst,
                                pin_feat, edge_feat, out, out_net, out_gcell);
}

// round 7
// speedup vs baseline: 1.1162x; 1.1162x over previous
#include <cuda_runtime.h>
#include <cuda_fp16.h>
#include <cstdint>

// Problem constants
static constexpr int N_CELL  = 50000;
static constexpr int N_NET   = 10000;
static constexpr int N_GCELL = 20000;
static constexpr int E       = 100000;
static constexpr int D       = 32;
static constexpr int N_PTOT  = N_NET + N_GCELL;                    // 30000 P rows
static constexpr int OUT_TOTAL = (N_CELL + N_NET + N_GCELL) * D;   // 2.56M

// Degree-counter layout
static constexpr int OFF_PINS_S   = 0;
static constexpr int OFF_PINS_D   = OFF_PINS_S + N_CELL;
static constexpr int OFF_CON_S    = OFF_PINS_D + N_NET;
static constexpr int OFF_CON_D    = OFF_CON_S + N_GCELL;
static constexpr int OFF_PT_S     = OFF_CON_D + N_GCELL;
static constexpr int OFF_PT_D     = OFF_PT_S + N_CELL;
static constexpr int OFF_PINNED_D = OFF_PT_D + N_GCELL;
static constexpr int OFF_PF_D     = OFF_PINNED_D + N_CELL;
static constexpr int DEG_TOTAL    = OFF_PF_D + N_CELL;             // 270000

// Scratch
__device__ int    g_deg[DEG_TOTAL];
__device__ float  g_feat_pins[N_CELL * D];
__device__ float  g_feat_pt[N_CELL * D];
__device__ float  g_feat_connect[N_GCELL * D];
__device__ __align__(16) __half g_P[(size_t)N_PTOT * 544];   // fp16 NNConv factor

// ---------------------------------------------------------------------------
// f32x2 packed-FMA helpers (Blackwell FFMA2)
typedef unsigned long long ull;
__device__ __forceinline__ ull f2pack(float lo, float hi) {
    ull r; asm("mov.b64 %0, {%1,%2};" : "=l"(r) : "f"(lo), "f"(hi)); return r;
}
__device__ __forceinline__ void f2unpack(ull v, float& lo, float& hi) {
    asm("mov.b64 {%0,%1}, %2;" : "=f"(lo), "=f"(hi) : "l"(v));
}
__device__ __forceinline__ ull ffma2(ull a, ull b, ull c) {
    ull d; asm("fma.rn.f32x2 %0, %1, %2, %3;" : "=l"(d) : "l"(a), "l"(b), "l"(c)); return d;
}

__device__ __forceinline__ void red_add_v4(float* addr, float x, float y, float z, float w) {
    asm volatile("red.global.add.v4.f32 [%0], {%1,%2,%3,%4};"
                 :: "l"(addr), "f"(x), "f"(y), "f"(z), "f"(w) : "memory");
}

__device__ __forceinline__ float4 ldh4(const __half* p) {
    uint2 u = __ldg(reinterpret_cast<const uint2*>(p));
    __half2 h0 = *reinterpret_cast<__half2*>(&u.x);
    __half2 h1 = *reinterpret_cast<__half2*>(&u.y);
    float2 f0 = __half22float2(h0);
    float2 f1 = __half22float2(h1);
    return make_float4(f0.x, f0.y, f1.x, f1.y);
}

// ---------------------------------------------------------------------------
// K1: fused init, vectorized x4: zero degree counters + bias sums into out.
static constexpr int INIT_V4 = OUT_TOTAL / 4;            // 640000
static constexpr int DEG_V4  = DEG_TOTAL / 4;            // 67500 (exact)
__global__ void init_fused_kernel(float* __restrict__ out,
                                  const float* __restrict__ b_pinned,
                                  const float* __restrict__ b_pf,
                                  const float* __restrict__ b_pins,
                                  const float* __restrict__ b_net,
                                  const float* __restrict__ b_connect,
                                  const float* __restrict__ b_pt) {
    int idx = blockIdx.x * blockDim.x + threadIdx.x;
    if (idx < DEG_V4)
        *reinterpret_cast<int4*>(&g_deg[idx * 4]) = make_int4(0, 0, 0, 0);
    if (idx >= INIT_V4) return;
    int elem = idx * 4;
    int row = elem >> 5;
    int j = elem & 31;       // 0,4,...,28
    float4 v;
    if (row < N_CELL)
        v = make_float4(b_pinned[j]   + b_pf[j],   b_pinned[j+1] + b_pf[j+1],
                        b_pinned[j+2] + b_pf[j+2], b_pinned[j+3] + b_pf[j+3]);
    else if (row < N_CELL + N_NET)
        v = make_float4(b_pins[j]   + b_net[j],   b_pins[j+1] + b_net[j+1],
                        b_pins[j+2] + b_net[j+2], b_pins[j+3] + b_net[j+3]);
    else
        v = make_float4(b_connect[j]   + b_pt[j],   b_connect[j+1] + b_pt[j+1],
                        b_connect[j+2] + b_pt[j+2], b_connect[j+3] + b_pt[j+3]);
    *reinterpret_cast<float4*>(&out[elem]) = v;
}

// ---------------------------------------------------------------------------
// K2: degree counting for all 8 (index, n) pairs
__global__ void degree_kernel(const int* __restrict__ pins_src, const int* __restrict__ pins_dst,
                              const int* __restrict__ connect_src, const int* __restrict__ connect_dst,
                              const int* __restrict__ pt_src, const int* __restrict__ pt_dst,
                              const int* __restrict__ pinned_dst, const int* __restrict__ pf_dst) {
    int e = blockIdx.x * blockDim.x + threadIdx.x;
    if (e >= E) return;
    atomicAdd(&g_deg[OFF_PINS_S   + pins_src[e]], 1);
    atomicAdd(&g_deg[OFF_PINS_D   + pins_dst[e]], 1);
    atomicAdd(&g_deg[OFF_CON_S    + connect_src[e]], 1);
    atomicAdd(&g_deg[OFF_CON_D    + connect_dst[e]], 1);
    atomicAdd(&g_deg[OFF_PT_S     + pt_src[e]], 1);
    atomicAdd(&g_deg[OFF_PT_D     + pt_dst[e]], 1);
    atomicAdd(&g_deg[OFF_PINNED_D + pinned_dst[e]], 1);
    atomicAdd(&g_deg[OFF_PF_D     + pf_dst[e]], 1);
}

// ---------------------------------------------------------------------------
// K3: unified dense mega-kernel (f32x2). Src-side GraphConv norm in epilogue.
static constexpr int NT_P    = (N_PTOT + 31) / 32;     // 938
static constexpr int NB_P    = NT_P * 5;               // 4690
static constexpr int NT_DUAL = (N_CELL + 31) / 32;     // 1563
static constexpr int NT_CON  = (N_GCELL + 31) / 32;    // 625
static constexpr int NT_NET  = (N_NET + 31) / 32;      // 313
static constexpr int NB_TOTAL = NB_P + NT_DUAL + NT_CON + NT_NET;

__global__ __launch_bounds__(256) void dense_kernel(
        const float* __restrict__ node_feat,
        const float* __restrict__ net_feat,
        const float* __restrict__ hanna_feat,
        const float* __restrict__ W_topo, const float* __restrict__ b_topo,
        const float* __restrict__ W_pins, const float* __restrict__ W_pt,
        const float* __restrict__ W_connect, const float* __restrict__ W_net,
        float* __restrict__ out_net) {
    __shared__ ull Asm2[32 * 33];    // (a,a) packed A tile
    __shared__ ull Wsm2[32 * 64];    // paired W columns

    int bid = blockIdx.x;
    int tid = threadIdx.x;

    int jobtype, tile, grp = 0;
    if (bid < NB_P)                        { jobtype = 0; tile = bid / 5; grp = bid % 5; }
    else if (bid < NB_P + NT_DUAL)         { jobtype = 1; tile = bid - NB_P; }
    else if (bid < NB_P + NT_DUAL + NT_CON){ jobtype = 2; tile = bid - NB_P - NT_DUAL; }
    else                                   { jobtype = 3; tile = bid - NB_P - NT_DUAL - NT_CON; }

    int n0 = tile * 32;
    int nrows = (jobtype == 0) ? N_PTOT : (jobtype == 1) ? N_CELL : (jobtype == 2) ? N_GCELL : N_NET;

    // ---- stage A (packed (a,a)) ----
    for (int idx = tid; idx < 32 * 32; idx += 256) {
        int r = idx >> 5, c = idx & 31;
        int node = n0 + r;
        float v = 0.0f;
        if (node < nrows) {
            if (jobtype == 0)      v = (node < N_NET) ? net_feat[node * 32 + c]
                                                      : hanna_feat[(node - N_NET) * 32 + c];
            else if (jobtype == 1) v = node_feat[node * 32 + c];
            else if (jobtype == 2) v = hanna_feat[node * 32 + c];
            else                   v = net_feat[node * 32 + c];
        }
        Asm2[r * 33 + c] = f2pack(v, v);
    }

    // ---- stage W pairs ----
    int npairs = (jobtype == 0) ? ((grp < 4) ? 64 : 16) : (jobtype == 1) ? 32 : 16;
    for (int idx = tid; idx < 32 * npairs; idx += 256) {
        int i = idx / npairs, p = idx % npairs;
        float2 w;
        if (jobtype == 0) {
            if (grp < 4) {
                int slot = grp * 4 + (p >> 4);
                w = *(const float2*)&W_topo[slot * 1024 + i * 32 + (p & 15) * 2];
            } else {
                w = *(const float2*)&b_topo[i * 32 + p * 2];
            }
        } else if (jobtype == 1) {
            w = (p < 16) ? *(const float2*)&W_pins[i * 32 + p * 2]
                         : *(const float2*)&W_pt[i * 32 + (p - 16) * 2];
        } else if (jobtype == 2) {
            w = *(const float2*)&W_connect[i * 32 + p * 2];
        } else {
            w = *(const float2*)&W_net[i * 32 + p * 2];
        }
        Wsm2[i * npairs + p] = f2pack(w.x, w.y);
    }
    __syncthreads();

    // ---- compute + store ----
    if (jobtype == 0 && grp < 4) {
        int tx = tid & 31, ty = tid >> 5;
        ull acc[4][2] = {};
#pragma unroll
        for (int i = 0; i < 32; i++) {
            ull w0 = Wsm2[i * 64 + tx];
            ull w1 = Wsm2[i * 64 + 32 + tx];
#pragma unroll
            for (int r = 0; r < 4; r++) {
                ull a = Asm2[(ty * 4 + r) * 33 + i];
                acc[r][0] = ffma2(a, w0, acc[r][0]);
                acc[r][1] = ffma2(a, w1, acc[r][1]);
            }
        }
#pragma unroll
        for (int r = 0; r < 4; r++) {
            int node = n0 + ty * 4 + r;
            if (node >= N_PTOT) break;
            float lo, hi;
            f2unpack(acc[r][0], lo, hi);
            *(__half2*)&g_P[(size_t)node * 544 + grp * 128 + tx * 2] = __floats2half2_rn(lo, hi);
            f2unpack(acc[r][1], lo, hi);
            *(__half2*)&g_P[(size_t)node * 544 + grp * 128 + 64 + tx * 2] = __floats2half2_rn(lo, hi);
        }
    } else if (jobtype == 1) {
        int tx = tid & 31, ty = tid >> 5;
        ull acc[4] = {};
#pragma unroll
        for (int i = 0; i < 32; i++) {
            ull w = Wsm2[i * 32 + tx];
#pragma unroll
            for (int r = 0; r < 4; r++)
                acc[r] = ffma2(Asm2[(ty * 4 + r) * 33 + i], w, acc[r]);
        }
#pragma unroll
        for (int r = 0; r < 4; r++) {
            int node = n0 + ty * 4 + r;
            if (node >= N_CELL) break;
            float lo, hi;
            f2unpack(acc[r], lo, hi);
            if (tx < 16) {
                float s = rsqrtf((float)max(g_deg[OFF_PINS_S + node], 1));
                *(float2*)&g_feat_pins[node * 32 + tx * 2] = make_float2(lo * s, hi * s);
            } else {
                float s = rsqrtf((float)max(g_deg[OFF_PT_S + node], 1));
                *(float2*)&g_feat_pt[node * 32 + (tx - 16) * 2] = make_float2(lo * s, hi * s);
            }
        }
    } else {
        int tx = tid & 15, tyy = tid >> 4;
        ull acc[2] = {};
#pragma unroll
        for (int i = 0; i < 32; i++) {
            ull w = Wsm2[i * 16 + tx];
            acc[0] = ffma2(Asm2[(tyy * 2 + 0) * 33 + i], w, acc[0]);
            acc[1] = ffma2(Asm2[(tyy * 2 + 1) * 33 + i], w, acc[1]);
        }
#pragma unroll
        for (int r = 0; r < 2; r++) {
            int node = n0 + tyy * 2 + r;
            if (node >= nrows) break;
            float lo, hi;
            f2unpack(acc[r], lo, hi);
            if (jobtype == 0) {
                *(__half2*)&g_P[(size_t)node * 544 + 512 + tx * 2] = __floats2half2_rn(lo, hi);
            } else if (jobtype == 2) {
                float s = rsqrtf((float)max(g_deg[OFF_CON_S + node], 1));
                *(float2*)&g_feat_connect[node * 32 + tx * 2] = make_float2(lo * s, hi * s);
            } else {
                // accumulate onto bias-initialized out_net
                float2* o = (float2*)&out_net[node * 32 + tx * 2];
                float2 cur = *o;
                *o = make_float2(cur.x + lo, cur.y + hi);
            }
        }
    }
}

// ---------------------------------------------------------------------------
// K4: all 5 edge relations, 4 edges/warp (8 lanes/edge) — round-3 proven form
// (ldh4 64-bit P loads, 40 regs, ~64% occupancy).
__global__ __launch_bounds__(256) void edge_kernel(
        const int* __restrict__ pins_src, const int* __restrict__ pins_dst,
        const int* __restrict__ con_src,  const int* __restrict__ con_dst,
        const int* __restrict__ pt_src,   const int* __restrict__ pt_dst,
        const int* __restrict__ pinned_src, const int* __restrict__ pinned_dst,
        const int* __restrict__ pf_src,   const int* __restrict__ pf_dst,
        const float* __restrict__ pin_feat, const float* __restrict__ edge_feat,
        float* __restrict__ out_cell, float* __restrict__ out_net, float* __restrict__ out_gcell) {
    int t = blockIdx.x * blockDim.x + threadIdx.x;
    int lane = t & 31;
    int e = ((t >> 5) << 2) + (lane >> 3);     // 4 edges per warp
    if (e >= E) return;
    int q = lane & 7;
    int baseLane = lane & 24;

    // --- GraphConv scatters: out[dst] += feat[src] * rsqrt(deg_dst) ---
    {
        int s = pins_src[e], d = pins_dst[e];
        float4 v = *reinterpret_cast<const float4*>(&g_feat_pins[s * 32 + q * 4]);
        float sc = rsqrtf((float)max(g_deg[OFF_PINS_D + d], 1));
        red_add_v4(out_net + d * 32 + q * 4, v.x * sc, v.y * sc, v.z * sc, v.w * sc);
    }
    {
        int s = con_src[e], d = con_dst[e];
        float4 v = *reinterpret_cast<const float4*>(&g_feat_connect[s * 32 + q * 4]);
        float sc = rsqrtf((float)max(g_deg[OFF_CON_D + d], 1));
        red_add_v4(out_gcell + d * 32 + q * 4, v.x * sc, v.y * sc, v.z * sc, v.w * sc);
    }
    {
        int s = pt_src[e], d = pt_dst[e];
        float4 v = *reinterpret_cast<const float4*>(&g_feat_pt[s * 32 + q * 4]);
        float sc = rsqrtf((float)max(g_deg[OFF_PT_D + d], 1));
        red_add_v4(out_gcell + d * 32 + q * 4, v.x * sc, v.y * sc, v.z * sc, v.w * sc);
    }

    // --- NNConv edges: out[dst] += (P_B[src] + sum_k ef[e,k]*P_k[src]) / deg_dst ---
    {
        int sA = pinned_src[e], dA = pinned_dst[e];
        int sB = pf_src[e] + N_NET, dB = pf_dst[e];
        float evA0 = pin_feat[e * 16 + q],  evA1 = pin_feat[e * 16 + 8 + q];
        float evB0 = edge_feat[e * 16 + q], evB1 = edge_feat[e * 16 + 8 + q];

        const __half* PA = g_P + (size_t)sA * 544;
        const __half* PB = g_P + (size_t)sB * 544;

        float4 mA = ldh4(PA + 512 + q * 4);
        float4 mB = ldh4(PB + 512 + q * 4);

#pragma unroll
        for (int k = 0; k < 16; k++) {
            float cA = __shfl_sync(0xffffffffu, (k < 8) ? evA0 : evA1, baseLane + (k & 7));
            float cB = __shfl_sync(0xffffffffu, (k < 8) ? evB0 : evB1, baseLane + (k & 7));
            float4 pA = ldh4(PA + k * 32 + q * 4);
            float4 pB = ldh4(PB + k * 32 + q * 4);
            mA.x = fmaf(cA, pA.x, mA.x); mA.y = fmaf(cA, pA.y, mA.y);
            mA.z = fmaf(cA, pA.z, mA.z); mA.w = fmaf(cA, pA.w, mA.w);
            mB.x = fmaf(cB, pB.x, mB.x); mB.y = fmaf(cB, pB.y, mB.y);
            mB.z = fmaf(cB, pB.z, mB.z); mB.w = fmaf(cB, pB.w, mB.w);
        }

        float invA = 1.0f / (float)max(g_deg[OFF_PINNED_D + dA], 1);
        float invB = 1.0f / (float)max(g_deg[OFF_PF_D + dB], 1);
        red_add_v4(out_cell + dA * 32 + q * 4, mA.x * invA, mA.y * invA, mA.z * invA, mA.w * invA);
        red_add_v4(out_cell + dB * 32 + q * 4, mB.x * invB, mB.y * invB, mB.z * invB, mB.w * invB);
    }
}

// ---------------------------------------------------------------------------
extern "C" void kernel_launch(void* const* d_in, const int* in_sizes, int n_in,
                              void* d_out, int out_size) {
    const float* node_feat   = (const float*)d_in[0];
    const float* net_feat    = (const float*)d_in[1];
    const float* pin_feat    = (const float*)d_in[2];
    const float* hanna_feat  = (const float*)d_in[3];
    const float* edge_feat   = (const float*)d_in[4];
    const int*   pins_src    = (const int*)d_in[5];
    const int*   pins_dst    = (const int*)d_in[6];
    const int*   pinned_src  = (const int*)d_in[7];
    const int*   pinned_dst  = (const int*)d_in[8];
    const int*   connect_src = (const int*)d_in[9];
    const int*   connect_dst = (const int*)d_in[10];
    const int*   pt_src      = (const int*)d_in[11];
    const int*   pt_dst      = (const int*)d_in[12];
    const int*   pf_src      = (const int*)d_in[13];
    const int*   pf_dst      = (const int*)d_in[14];
    const float* W_net       = (const float*)d_in[15];
    const float* b_net       = (const float*)d_in[16];
    const float* W_topo      = (const float*)d_in[17];
    const float* b_topo      = (const float*)d_in[18];
    const float* W_pins      = (const float*)d_in[19];
    const float* b_pins      = (const float*)d_in[20];
    const float* W_connect   = (const float*)d_in[21];
    const float* b_connect   = (const float*)d_in[22];
    const float* W_pt        = (const float*)d_in[23];
    const float* b_pt        = (const float*)d_in[24];
    const float* b_pinned    = (const float*)d_in[25];
    const float* b_pf        = (const float*)d_in[26];

    float* out       = (float*)d_out;
    float* out_net   = out + (size_t)N_CELL * D;
    float* out_gcell = out + (size_t)(N_CELL + N_NET) * D;

    // K1: fused init (zero degrees + bias-sum output init), vectorized
    init_fused_kernel<<<(INIT_V4 + 255) / 256, 256>>>(out, b_pinned, b_pf, b_pins, b_net,
                                                      b_connect, b_pt);

    // K2: degrees
    degree_kernel<<<(E + 255) / 256, 256>>>(pins_src, pins_dst, connect_src, connect_dst,
                                            pt_src, pt_dst, pinned_dst, pf_dst);

    // K3: all dense GEMMs (f32x2, src norm in epilogue)
    dense_kernel<<<NB_TOTAL, 256>>>(node_feat, net_feat, hanna_feat,
                                    W_topo, b_topo, W_pins, W_pt, W_connect, W_net, out_net);

    // K4: all 5 edge relations (round-3 proven kernel)
    const int EGRID = (E / 4 * 32 + 255) / 256;   // 3125 blocks
    edge_kernel<<<EGRID, 256>>>(pins_src, pins_dst, connect_src, connect_dst,
                                pt_src, pt_dst, pinned_src, pinned_dst, pf_src, pf_dst,
                                pin_feat, edge_feat, out, out_net, out_gcell);
}

// round 8
// speedup vs baseline: 1.1328x; 1.0149x over previous
#include <cuda_runtime.h>
#include <cuda_fp16.h>
#include <cstdint>

// Problem constants
static constexpr int N_CELL  = 50000;
static constexpr int N_NET   = 10000;
static constexpr int N_GCELL = 20000;
static constexpr int E       = 100000;
static constexpr int D       = 32;
static constexpr int N_PTOT  = N_NET + N_GCELL;                    // 30000 P rows
static constexpr int OUT_TOTAL = (N_CELL + N_NET + N_GCELL) * D;   // 2.56M

// Degree-counter layout
static constexpr int OFF_PINS_S   = 0;
static constexpr int OFF_PINS_D   = OFF_PINS_S + N_CELL;
static constexpr int OFF_CON_S    = OFF_PINS_D + N_NET;
static constexpr int OFF_CON_D    = OFF_CON_S + N_GCELL;
static constexpr int OFF_PT_S     = OFF_CON_D + N_GCELL;
static constexpr int OFF_PT_D     = OFF_PT_S + N_CELL;
static constexpr int OFF_PINNED_D = OFF_PT_D + N_GCELL;
static constexpr int OFF_PF_D     = OFF_PINNED_D + N_CELL;
static constexpr int DEG_TOTAL    = OFF_PF_D + N_CELL;             // 270000

// Scratch
__device__ int    g_deg[DEG_TOTAL];
__device__ float  g_feat_pins[N_CELL * D];
__device__ float  g_feat_pt[N_CELL * D];
__device__ float  g_feat_connect[N_GCELL * D];
__device__ __align__(16) __half g_P[(size_t)N_PTOT * 544];   // fp16 NNConv factor

// ---------------------------------------------------------------------------
// f32x2 packed-FMA helpers (Blackwell FFMA2)
typedef unsigned long long ull;
__device__ __forceinline__ ull f2pack(float lo, float hi) {
    ull r; asm("mov.b64 %0, {%1,%2};" : "=l"(r) : "f"(lo), "f"(hi)); return r;
}
__device__ __forceinline__ void f2unpack(ull v, float& lo, float& hi) {
    asm("mov.b64 {%0,%1}, %2;" : "=f"(lo), "=f"(hi) : "l"(v));
}
__device__ __forceinline__ ull ffma2(ull a, ull b, ull c) {
    ull d; asm("fma.rn.f32x2 %0, %1, %2, %3;" : "=l"(d) : "l"(a), "l"(b), "l"(c)); return d;
}

__device__ __forceinline__ void red_add_v4(float* addr, float x, float y, float z, float w) {
    asm volatile("red.global.add.v4.f32 [%0], {%1,%2,%3,%4};"
                 :: "l"(addr), "f"(x), "f"(y), "f"(z), "f"(w) : "memory");
}

__device__ __forceinline__ float4 ldh4(const __half* p) {
    uint2 u = __ldg(reinterpret_cast<const uint2*>(p));
    __half2 h0 = *reinterpret_cast<__half2*>(&u.x);
    __half2 h1 = *reinterpret_cast<__half2*>(&u.y);
    float2 f0 = __half22float2(h0);
    float2 f1 = __half22float2(h1);
    return make_float4(f0.x, f0.y, f1.x, f1.y);
}

__device__ __forceinline__ unsigned h2u(float lo, float hi) {
    __half2 h = __floats2half2_rn(lo, hi);
    return *reinterpret_cast<unsigned*>(&h);
}

// ---------------------------------------------------------------------------
// K1: fused init, vectorized x4: zero degree counters + bias sums into out.
static constexpr int INIT_V4 = OUT_TOTAL / 4;            // 640000
static constexpr int DEG_V4  = DEG_TOTAL / 4;            // 67500 (exact)
__global__ void init_fused_kernel(float* __restrict__ out,
                                  const float* __restrict__ b_pinned,
                                  const float* __restrict__ b_pf,
                                  const float* __restrict__ b_pins,
                                  const float* __restrict__ b_net,
                                  const float* __restrict__ b_connect,
                                  const float* __restrict__ b_pt) {
    int idx = blockIdx.x * blockDim.x + threadIdx.x;
    if (idx < DEG_V4)
        *reinterpret_cast<int4*>(&g_deg[idx * 4]) = make_int4(0, 0, 0, 0);
    if (idx >= INIT_V4) return;
    int elem = idx * 4;
    int row = elem >> 5;
    int j = elem & 31;
    float4 v;
    if (row < N_CELL)
        v = make_float4(b_pinned[j]   + b_pf[j],   b_pinned[j+1] + b_pf[j+1],
                        b_pinned[j+2] + b_pf[j+2], b_pinned[j+3] + b_pf[j+3]);
    else if (row < N_CELL + N_NET)
        v = make_float4(b_pins[j]   + b_net[j],   b_pins[j+1] + b_net[j+1],
                        b_pins[j+2] + b_net[j+2], b_pins[j+3] + b_net[j+3]);
    else
        v = make_float4(b_connect[j]   + b_pt[j],   b_connect[j+1] + b_pt[j+1],
                        b_connect[j+2] + b_pt[j+2], b_connect[j+3] + b_pt[j+3]);
    *reinterpret_cast<float4*>(&out[elem]) = v;
}

// ---------------------------------------------------------------------------
// K2: degree counting for all 8 (index, n) pairs
__global__ void degree_kernel(const int* __restrict__ pins_src, const int* __restrict__ pins_dst,
                              const int* __restrict__ connect_src, const int* __restrict__ connect_dst,
                              const int* __restrict__ pt_src, const int* __restrict__ pt_dst,
                              const int* __restrict__ pinned_dst, const int* __restrict__ pf_dst) {
    int e = blockIdx.x * blockDim.x + threadIdx.x;
    if (e >= E) return;
    atomicAdd(&g_deg[OFF_PINS_S   + pins_src[e]], 1);
    atomicAdd(&g_deg[OFF_PINS_D   + pins_dst[e]], 1);
    atomicAdd(&g_deg[OFF_CON_S    + connect_src[e]], 1);
    atomicAdd(&g_deg[OFF_CON_D    + connect_dst[e]], 1);
    atomicAdd(&g_deg[OFF_PT_S     + pt_src[e]], 1);
    atomicAdd(&g_deg[OFF_PT_D     + pt_dst[e]], 1);
    atomicAdd(&g_deg[OFF_PINNED_D + pinned_dst[e]], 1);
    atomicAdd(&g_deg[OFF_PF_D     + pf_dst[e]], 1);
}

// ---------------------------------------------------------------------------
// K3: P-GEMM (slots 0..15 = 512 cols) with 8x8 per-thread tiles, f32x2.
// [net;hanna] (30000 x 32) @ W_topo (32 x 512).  Block tile: 64 rows x 256 cols.
// A staged k-major PRE-DUPLICATED as (a,a) ulls -> both operands via LDS.128.
// Per k per thread: 6 LDS.128 + 32 ffma2 (vs 6 LDS per 8 ffma2 previously).
static constexpr int PG_TILES  = (N_PTOT + 63) / 64;   // 469
static constexpr int PG_BLOCKS = PG_TILES * 2;         // 938

__global__ __launch_bounds__(256, 2) void pgemm_kernel(
        const float* __restrict__ net_feat,
        const float* __restrict__ hanna_feat,
        const float* __restrict__ W_topo) {
    __shared__ ull Asm[32 * 64];     // [k][row], (a,a) duplicated — 16 KB
    __shared__ ull Wsm[32 * 128];    // [k][colpair] — 32 KB   (total 48 KB exactly)

    int tile    = blockIdx.x >> 1;
    int colbase = (blockIdx.x & 1) * 256;     // global col offset (0 or 256)
    int n0      = tile * 64;
    int tid     = threadIdx.x;

    // ---- stage A: coalesced row reads, scatter to k-major duplicated ----
    for (int g = tid; g < 512; g += 256) {     // 64 rows x 8 segs(4 floats)
        int row = g >> 3, seg = g & 7;
        int node = n0 + row;
        float4 x = make_float4(0.f, 0.f, 0.f, 0.f);
        if (node < N_PTOT) {
            const float* src = (node < N_NET) ? &net_feat[node * 32 + seg * 4]
                                              : &hanna_feat[(node - N_NET) * 32 + seg * 4];
            x = *reinterpret_cast<const float4*>(src);
        }
        Asm[(seg * 4 + 0) * 64 + row] = f2pack(x.x, x.x);
        Asm[(seg * 4 + 1) * 64 + row] = f2pack(x.y, x.y);
        Asm[(seg * 4 + 2) * 64 + row] = f2pack(x.z, x.z);
        Asm[(seg * 4 + 3) * 64 + row] = f2pack(x.w, x.w);
    }

    // ---- stage W: 16B granules (4 cols = 2 pairs each) ----
    for (int g = tid; g < 2048; g += 256) {    // 32 k x 64 granules
        int k = g >> 6, p0 = (g & 63) * 2;     // pair index 0..126 step 2
        int c0 = colbase + p0 * 2;             // global col (multiple of 4)
        int slot = c0 >> 5, j = c0 & 31;
        float4 w = *reinterpret_cast<const float4*>(&W_topo[slot * 1024 + k * 32 + j]);
        Wsm[k * 128 + p0]     = f2pack(w.x, w.y);
        Wsm[k * 128 + p0 + 1] = f2pack(w.z, w.w);
    }
    __syncthreads();

    // thread tiling: warp = (wr 0..1, wc 0..3); lane = (ty 0..3, tx 0..7)
    int w  = tid >> 5;
    int wr = w >> 2, wc = w & 3;
    int lane = tid & 31;
    int ty = lane >> 3, tx = lane & 7;
    int rbase = wr * 32 + ty * 8;              // 8 rows
    int pb    = wc * 32 + tx * 4;              // 4 col-pairs (8 cols)

    ull acc[8][4];
#pragma unroll
    for (int r = 0; r < 8; r++)
#pragma unroll
        for (int c = 0; c < 4; c++) acc[r][c] = 0ull;

#pragma unroll 4
    for (int k = 0; k < 32; k++) {
        const ulonglong2* Ap = reinterpret_cast<const ulonglong2*>(&Asm[k * 64 + rbase]);
        const ulonglong2* Wp = reinterpret_cast<const ulonglong2*>(&Wsm[k * 128 + pb]);
        ulonglong2 a01 = Ap[0], a23 = Ap[1], a45 = Ap[2], a67 = Ap[3];
        ulonglong2 w01 = Wp[0], w23 = Wp[1];
        ull a[8] = {a01.x, a01.y, a23.x, a23.y, a45.x, a45.y, a67.x, a67.y};
        ull wv[4] = {w01.x, w01.y, w23.x, w23.y};
#pragma unroll
        for (int r = 0; r < 8; r++)
#pragma unroll
            for (int c = 0; c < 4; c++)
                acc[r][c] = ffma2(a[r], wv[c], acc[r][c]);
    }

    // ---- epilogue: fp16 pack, 16B stores ----
    int colg = colbase + wc * 64 + tx * 8;     // global col base for this thread
#pragma unroll
    for (int r = 0; r < 8; r++) {
        int node = n0 + rbase + r;
        if (node >= N_PTOT) break;
        float l0, h0, l1, h1, l2, h2, l3, h3;
        f2unpack(acc[r][0], l0, h0);
        f2unpack(acc[r][1], l1, h1);
        f2unpack(acc[r][2], l2, h2);
        f2unpack(acc[r][3], l3, h3);
        uint4 o = make_uint4(h2u(l0, h0), h2u(l1, h1), h2u(l2, h2), h2u(l3, h3));
        *reinterpret_cast<uint4*>(&g_P[(size_t)node * 544 + colg]) = o;
    }
}

// ---------------------------------------------------------------------------
// K4: remaining dense jobs (f32x2): P bias slot, dual node transform,
// connect transform, net transform. Src-side GraphConv norm in epilogue.
static constexpr int NT_P    = (N_PTOT + 31) / 32;     // 938 (bias slot)
static constexpr int NT_DUAL = (N_CELL + 31) / 32;     // 1563
static constexpr int NT_CON  = (N_GCELL + 31) / 32;    // 625
static constexpr int NT_NET  = (N_NET + 31) / 32;      // 313
static constexpr int NB_REST = NT_P + NT_DUAL + NT_CON + NT_NET;   // 3439

__global__ __launch_bounds__(256) void dense_rest_kernel(
        const float* __restrict__ node_feat,
        const float* __restrict__ net_feat,
        const float* __restrict__ hanna_feat,
        const float* __restrict__ b_topo,
        const float* __restrict__ W_pins, const float* __restrict__ W_pt,
        const float* __restrict__ W_connect, const float* __restrict__ W_net,
        float* __restrict__ out_net) {
    __shared__ ull Asm2[32 * 33];    // (a,a) packed A tile
    __shared__ ull Wsm2[32 * 32];    // paired W columns (max 32 pairs)

    int bid = blockIdx.x;
    int tid = threadIdx.x;

    int jobtype, tile;
    if (bid < NT_P)                          { jobtype = 0; tile = bid; }
    else if (bid < NT_P + NT_DUAL)           { jobtype = 1; tile = bid - NT_P; }
    else if (bid < NT_P + NT_DUAL + NT_CON)  { jobtype = 2; tile = bid - NT_P - NT_DUAL; }
    else                                     { jobtype = 3; tile = bid - NT_P - NT_DUAL - NT_CON; }

    int n0 = tile * 32;
    int nrows = (jobtype == 0) ? N_PTOT : (jobtype == 1) ? N_CELL : (jobtype == 2) ? N_GCELL : N_NET;

    // ---- stage A (packed (a,a)) ----
    for (int idx = tid; idx < 32 * 32; idx += 256) {
        int r = idx >> 5, c = idx & 31;
        int node = n0 + r;
        float v = 0.0f;
        if (node < nrows) {
            if (jobtype == 0)      v = (node < N_NET) ? net_feat[node * 32 + c]
                                                      : hanna_feat[(node - N_NET) * 32 + c];
            else if (jobtype == 1) v = node_feat[node * 32 + c];
            else if (jobtype == 2) v = hanna_feat[node * 32 + c];
            else                   v = net_feat[node * 32 + c];
        }
        Asm2[r * 33 + c] = f2pack(v, v);
    }

    // ---- stage W pairs ----
    int npairs = (jobtype == 1) ? 32 : 16;
    for (int idx = tid; idx < 32 * npairs; idx += 256) {
        int i = idx / npairs, p = idx % npairs;
        float2 w;
        if (jobtype == 0)      w = *(const float2*)&b_topo[i * 32 + p * 2];
        else if (jobtype == 1) w = (p < 16) ? *(const float2*)&W_pins[i * 32 + p * 2]
                                            : *(const float2*)&W_pt[i * 32 + (p - 16) * 2];
        else if (jobtype == 2) w = *(const float2*)&W_connect[i * 32 + p * 2];
        else                   w = *(const float2*)&W_net[i * 32 + p * 2];
        Wsm2[i * npairs + p] = f2pack(w.x, w.y);
    }
    __syncthreads();

    // ---- compute + store ----
    if (jobtype == 1) {
        int tx = tid & 31, ty = tid >> 5;
        ull acc[4] = {};
#pragma unroll
        for (int i = 0; i < 32; i++) {
            ull w = Wsm2[i * 32 + tx];
#pragma unroll
            for (int r = 0; r < 4; r++)
                acc[r] = ffma2(Asm2[(ty * 4 + r) * 33 + i], w, acc[r]);
        }
#pragma unroll
        for (int r = 0; r < 4; r++) {
            int node = n0 + ty * 4 + r;
            if (node >= N_CELL) break;
            float lo, hi;
            f2unpack(acc[r], lo, hi);
            if (tx < 16) {
                float s = rsqrtf((float)max(g_deg[OFF_PINS_S + node], 1));
                *(float2*)&g_feat_pins[node * 32 + tx * 2] = make_float2(lo * s, hi * s);
            } else {
                float s = rsqrtf((float)max(g_deg[OFF_PT_S + node], 1));
                *(float2*)&g_feat_pt[node * 32 + (tx - 16) * 2] = make_float2(lo * s, hi * s);
            }
        }
    } else {
        int tx = tid & 15, tyy = tid >> 4;
        ull acc[2] = {};
#pragma unroll
        for (int i = 0; i < 32; i++) {
            ull w = Wsm2[i * 16 + tx];
            acc[0] = ffma2(Asm2[(tyy * 2 + 0) * 33 + i], w, acc[0]);
            acc[1] = ffma2(Asm2[(tyy * 2 + 1) * 33 + i], w, acc[1]);
        }
#pragma unroll
        for (int r = 0; r < 2; r++) {
            int node = n0 + tyy * 2 + r;
            if (node >= nrows) break;
            float lo, hi;
            f2unpack(acc[r], lo, hi);
            if (jobtype == 0) {
                *(__half2*)&g_P[(size_t)node * 544 + 512 + tx * 2] = __floats2half2_rn(lo, hi);
            } else if (jobtype == 2) {
                float s = rsqrtf((float)max(g_deg[OFF_CON_S + node], 1));
                *(float2*)&g_feat_connect[node * 32 + tx * 2] = make_float2(lo * s, hi * s);
            } else {
                float2* o = (float2*)&out_net[node * 32 + tx * 2];
                float2 cur = *o;
                *o = make_float2(cur.x + lo, cur.y + hi);
            }
        }
    }
}

// ---------------------------------------------------------------------------
// K5: all 5 edge relations, 4 edges/warp (8 lanes/edge) — R3/R7 proven form.
__global__ __launch_bounds__(256) void edge_kernel(
        const int* __restrict__ pins_src, const int* __restrict__ pins_dst,
        const int* __restrict__ con_src,  const int* __restrict__ con_dst,
        const int* __restrict__ pt_src,   const int* __restrict__ pt_dst,
        const int* __restrict__ pinned_src, const int* __restrict__ pinned_dst,
        const int* __restrict__ pf_src,   const int* __restrict__ pf_dst,
        const float* __restrict__ pin_feat, const float* __restrict__ edge_feat,
        float* __restrict__ out_cell, float* __restrict__ out_net, float* __restrict__ out_gcell) {
    int t = blockIdx.x * blockDim.x + threadIdx.x;
    int lane = t & 31;
    int e = ((t >> 5) << 2) + (lane >> 3);     // 4 edges per warp
    if (e >= E) return;
    int q = lane & 7;
    int baseLane = lane & 24;

    // --- GraphConv scatters: out[dst] += feat[src] * rsqrt(deg_dst) ---
    {
        int s = pins_src[e], d = pins_dst[e];
        float4 v = *reinterpret_cast<const float4*>(&g_feat_pins[s * 32 + q * 4]);
        float sc = rsqrtf((float)max(g_deg[OFF_PINS_D + d], 1));
        red_add_v4(out_net + d * 32 + q * 4, v.x * sc, v.y * sc, v.z * sc, v.w * sc);
    }
    {
        int s = con_src[e], d = con_dst[e];
        float4 v = *reinterpret_cast<const float4*>(&g_feat_connect[s * 32 + q * 4]);
        float sc = rsqrtf((float)max(g_deg[OFF_CON_D + d], 1));
        red_add_v4(out_gcell + d * 32 + q * 4, v.x * sc, v.y * sc, v.z * sc, v.w * sc);
    }
    {
        int s = pt_src[e], d = pt_dst[e];
        float4 v = *reinterpret_cast<const float4*>(&g_feat_pt[s * 32 + q * 4]);
        float sc = rsqrtf((float)max(g_deg[OFF_PT_D + d], 1));
        red_add_v4(out_gcell + d * 32 + q * 4, v.x * sc, v.y * sc, v.z * sc, v.w * sc);
    }

    // --- NNConv edges: out[dst] += (P_B[src] + sum_k ef[e,k]*P_k[src]) / deg_dst ---
    {
        int sA = pinned_src[e], dA = pinned_dst[e];
        int sB = pf_src[e] + N_NET, dB = pf_dst[e];
        float evA0 = pin_feat[e * 16 + q],  evA1 = pin_feat[e * 16 + 8 + q];
        float evB0 = edge_feat[e * 16 + q], evB1 = edge_feat[e * 16 + 8 + q];

        const __half* PA = g_P + (size_t)sA * 544;
        const __half* PB = g_P + (size_t)sB * 544;

        float4 mA = ldh4(PA + 512 + q * 4);
        float4 mB = ldh4(PB + 512 + q * 4);

#pragma unroll
        for (int k = 0; k < 16; k++) {
            float cA = __shfl_sync(0xffffffffu, (k < 8) ? evA0 : evA1, baseLane + (k & 7));
            float cB = __shfl_sync(0xffffffffu, (k < 8) ? evB0 : evB1, baseLane + (k & 7));
            float4 pA = ldh4(PA + k * 32 + q * 4);
            float4 pB = ldh4(PB + k * 32 + q * 4);
            mA.x = fmaf(cA, pA.x, mA.x); mA.y = fmaf(cA, pA.y, mA.y);
            mA.z = fmaf(cA, pA.z, mA.z); mA.w = fmaf(cA, pA.w, mA.w);
            mB.x = fmaf(cB, pB.x, mB.x); mB.y = fmaf(cB, pB.y, mB.y);
            mB.z = fmaf(cB, pB.z, mB.z); mB.w = fmaf(cB, pB.w, mB.w);
        }

        float invA = 1.0f / (float)max(g_deg[OFF_PINNED_D + dA], 1);
        float invB = 1.0f / (float)max(g_deg[OFF_PF_D + dB], 1);
        red_add_v4(out_cell + dA * 32 + q * 4, mA.x * invA, mA.y * invA, mA.z * invA, mA.w * invA);
        red_add_v4(out_cell + dB * 32 + q * 4, mB.x * invB, mB.y * invB, mB.z * invB, mB.w * invB);
    }
}

// ---------------------------------------------------------------------------
extern "C" void kernel_launch(void* const* d_in, const int* in_sizes, int n_in,
                              void* d_out, int out_size) {
    const float* node_feat   = (const float*)d_in[0];
    const float* net_feat    = (const float*)d_in[1];
    const float* pin_feat    = (const float*)d_in[2];
    const float* hanna_feat  = (const float*)d_in[3];
    const float* edge_feat   = (const float*)d_in[4];
    const int*   pins_src    = (const int*)d_in[5];
    const int*   pins_dst    = (const int*)d_in[6];
    const int*   pinned_src  = (const int*)d_in[7];
    const int*   pinned_dst  = (const int*)d_in[8];
    const int*   connect_src = (const int*)d_in[9];
    const int*   connect_dst = (const int*)d_in[10];
    const int*   pt_src      = (const int*)d_in[11];
    const int*   pt_dst      = (const int*)d_in[12];
    const int*   pf_src      = (const int*)d_in[13];
    const int*   pf_dst      = (const int*)d_in[14];
    const float* W_net       = (const float*)d_in[15];
    const float* b_net       = (const float*)d_in[16];
    const float* W_topo      = (const float*)d_in[17];
    const float* b_topo      = (const float*)d_in[18];
    const float* W_pins      = (const float*)d_in[19];
    const float* b_pins      = (const float*)d_in[20];
    const float* W_connect   = (const float*)d_in[21];
    const float* b_connect   = (const float*)d_in[22];
    const float* W_pt        = (const float*)d_in[23];
    const float* b_pt        = (const float*)d_in[24];
    const float* b_pinned    = (const float*)d_in[25];
    const float* b_pf        = (const float*)d_in[26];

    float* out       = (float*)d_out;
    float* out_net   = out + (size_t)N_CELL * D;
    float* out_gcell = out + (size_t)(N_CELL + N_NET) * D;

    // K1: fused init (zero degrees + bias-sum output init), vectorized
    init_fused_kernel<<<(INIT_V4 + 255) / 256, 256>>>(out, b_pinned, b_pf, b_pins, b_net,
                                                      b_connect, b_pt);

    // K2: degrees
    degree_kernel<<<(E + 255) / 256, 256>>>(pins_src, pins_dst, connect_src, connect_dst,
                                            pt_src, pt_dst, pinned_dst, pf_dst);

    // K3: P-GEMM slots 0..15 (new 8x8-tile f32x2 kernel)
    pgemm_kernel<<<PG_BLOCKS, 256>>>(net_feat, hanna_feat, W_topo);

    // K4: remaining dense jobs (bias slot + transforms)
    dense_rest_kernel<<<NB_REST, 256>>>(node_feat, net_feat, hanna_feat,
                                        b_topo, W_pins, W_pt, W_connect, W_net, out_net);

    // K5: all 5 edge relations (proven kernel)
    const int EGRID = (E / 4 * 32 + 255) / 256;   // 3125 blocks
    edge_kernel<<<EGRID, 256>>>(pins_src, pins_dst, connect_src, connect_dst,
                                pt_src, pt_dst, pinned_src, pinned_dst, pf_src, pf_dst,
                                pin_feat, edge_feat, out, out_net, out_gcell);
}

// round 9
// speedup vs baseline: 1.1525x; 1.0174x over previous
#include <cuda_runtime.h>
#include <cuda_fp16.h>
#include <cstdint>

// Problem constants
static constexpr int N_CELL  = 50000;
static constexpr int N_NET   = 10000;
static constexpr int N_GCELL = 20000;
static constexpr int E       = 100000;
static constexpr int D       = 32;
static constexpr int N_PTOT  = N_NET + N_GCELL;                    // 30000 P rows
static constexpr int OUT_TOTAL = (N_CELL + N_NET + N_GCELL) * D;   // 2.56M

// Degree-counter layout
static constexpr int OFF_PINS_S   = 0;
static constexpr int OFF_PINS_D   = OFF_PINS_S + N_CELL;
static constexpr int OFF_CON_S    = OFF_PINS_D + N_NET;
static constexpr int OFF_CON_D    = OFF_CON_S + N_GCELL;
static constexpr int OFF_PT_S     = OFF_CON_D + N_GCELL;
static constexpr int OFF_PT_D     = OFF_PT_S + N_CELL;
static constexpr int OFF_PINNED_D = OFF_PT_D + N_GCELL;
static constexpr int OFF_PF_D     = OFF_PINNED_D + N_CELL;
static constexpr int DEG_TOTAL    = OFF_PF_D + N_CELL;             // 270000

// Scratch
__device__ int    g_deg[DEG_TOTAL];
__device__ float  g_feat_pins[N_CELL * D];
__device__ float  g_feat_pt[N_CELL * D];
__device__ float  g_feat_connect[N_GCELL * D];
__device__ __align__(16) __half g_P[(size_t)N_PTOT * 544];   // fp16 NNConv factor

// ---------------------------------------------------------------------------
// f32x2 packed-FMA helpers (Blackwell FFMA2)
typedef unsigned long long ull;
__device__ __forceinline__ ull f2pack(float lo, float hi) {
    ull r; asm("mov.b64 %0, {%1,%2};" : "=l"(r) : "f"(lo), "f"(hi)); return r;
}
__device__ __forceinline__ void f2unpack(ull v, float& lo, float& hi) {
    asm("mov.b64 {%0,%1}, %2;" : "=f"(lo), "=f"(hi) : "l"(v));
}
__device__ __forceinline__ ull ffma2(ull a, ull b, ull c) {
    ull d; asm("fma.rn.f32x2 %0, %1, %2, %3;" : "=l"(d) : "l"(a), "l"(b), "l"(c)); return d;
}

__device__ __forceinline__ void red_add_v4(float* addr, float x, float y, float z, float w) {
    asm volatile("red.global.add.v4.f32 [%0], {%1,%2,%3,%4};"
                 :: "l"(addr), "f"(x), "f"(y), "f"(z), "f"(w) : "memory");
}

__device__ __forceinline__ float4 ldh4(const __half* p) {
    uint2 u = __ldg(reinterpret_cast<const uint2*>(p));
    __half2 h0 = *reinterpret_cast<__half2*>(&u.x);
    __half2 h1 = *reinterpret_cast<__half2*>(&u.y);
    float2 f0 = __half22float2(h0);
    float2 f1 = __half22float2(h1);
    return make_float4(f0.x, f0.y, f1.x, f1.y);
}

__device__ __forceinline__ unsigned h2u(float lo, float hi) {
    __half2 h = __floats2half2_rn(lo, hi);
    return *reinterpret_cast<unsigned*>(&h);
}

// ---------------------------------------------------------------------------
// K1: fused init, vectorized x4: zero degree counters + bias sums into out.
static constexpr int INIT_V4 = OUT_TOTAL / 4;            // 640000
static constexpr int DEG_V4  = DEG_TOTAL / 4;            // 67500 (exact)
__global__ void init_fused_kernel(float* __restrict__ out,
                                  const float* __restrict__ b_pinned,
                                  const float* __restrict__ b_pf,
                                  const float* __restrict__ b_pins,
                                  const float* __restrict__ b_net,
                                  const float* __restrict__ b_connect,
                                  const float* __restrict__ b_pt) {
    int idx = blockIdx.x * blockDim.x + threadIdx.x;
    if (idx < DEG_V4)
        *reinterpret_cast<int4*>(&g_deg[idx * 4]) = make_int4(0, 0, 0, 0);
    if (idx >= INIT_V4) return;
    int elem = idx * 4;
    int row = elem >> 5;
    int j = elem & 31;
    float4 v;
    if (row < N_CELL)
        v = make_float4(b_pinned[j]   + b_pf[j],   b_pinned[j+1] + b_pf[j+1],
                        b_pinned[j+2] + b_pf[j+2], b_pinned[j+3] + b_pf[j+3]);
    else if (row < N_CELL + N_NET)
        v = make_float4(b_pins[j]   + b_net[j],   b_pins[j+1] + b_net[j+1],
                        b_pins[j+2] + b_net[j+2], b_pins[j+3] + b_net[j+3]);
    else
        v = make_float4(b_connect[j]   + b_pt[j],   b_connect[j+1] + b_pt[j+1],
                        b_connect[j+2] + b_pt[j+2], b_connect[j+3] + b_pt[j+3]);
    *reinterpret_cast<float4*>(&out[elem]) = v;
}

// ---------------------------------------------------------------------------
// K2: degree counting for all 8 (index, n) pairs
__global__ void degree_kernel(const int* __restrict__ pins_src, const int* __restrict__ pins_dst,
                              const int* __restrict__ connect_src, const int* __restrict__ connect_dst,
                              const int* __restrict__ pt_src, const int* __restrict__ pt_dst,
                              const int* __restrict__ pinned_dst, const int* __restrict__ pf_dst) {
    int e = blockIdx.x * blockDim.x + threadIdx.x;
    if (e >= E) return;
    atomicAdd(&g_deg[OFF_PINS_S   + pins_src[e]], 1);
    atomicAdd(&g_deg[OFF_PINS_D   + pins_dst[e]], 1);
    atomicAdd(&g_deg[OFF_CON_S    + connect_src[e]], 1);
    atomicAdd(&g_deg[OFF_CON_D    + connect_dst[e]], 1);
    atomicAdd(&g_deg[OFF_PT_S     + pt_src[e]], 1);
    atomicAdd(&g_deg[OFF_PT_D     + pt_dst[e]], 1);
    atomicAdd(&g_deg[OFF_PINNED_D + pinned_dst[e]], 1);
    atomicAdd(&g_deg[OFF_PF_D     + pf_dst[e]], 1);
}

// ---------------------------------------------------------------------------
// K3: P-GEMM (slots 0..15 = 512 cols), 8x8 per-thread tiles, f32x2 (R8 proven).
static constexpr int PG_TILES  = (N_PTOT + 63) / 64;   // 469
static constexpr int PG_BLOCKS = PG_TILES * 2;         // 938

__global__ __launch_bounds__(256, 2) void pgemm_kernel(
        const float* __restrict__ net_feat,
        const float* __restrict__ hanna_feat,
        const float* __restrict__ W_topo) {
    __shared__ ull Asm[32 * 64];     // [k][row], (a,a) duplicated — 16 KB
    __shared__ ull Wsm[32 * 128];    // [k][colpair] — 32 KB

    int tile    = blockIdx.x >> 1;
    int colbase = (blockIdx.x & 1) * 256;
    int n0      = tile * 64;
    int tid     = threadIdx.x;

    for (int g = tid; g < 512; g += 256) {
        int row = g >> 3, seg = g & 7;
        int node = n0 + row;
        float4 x = make_float4(0.f, 0.f, 0.f, 0.f);
        if (node < N_PTOT) {
            const float* src = (node < N_NET) ? &net_feat[node * 32 + seg * 4]
                                              : &hanna_feat[(node - N_NET) * 32 + seg * 4];
            x = *reinterpret_cast<const float4*>(src);
        }
        Asm[(seg * 4 + 0) * 64 + row] = f2pack(x.x, x.x);
        Asm[(seg * 4 + 1) * 64 + row] = f2pack(x.y, x.y);
        Asm[(seg * 4 + 2) * 64 + row] = f2pack(x.z, x.z);
        Asm[(seg * 4 + 3) * 64 + row] = f2pack(x.w, x.w);
    }

    for (int g = tid; g < 2048; g += 256) {
        int k = g >> 6, p0 = (g & 63) * 2;
        int c0 = colbase + p0 * 2;
        int slot = c0 >> 5, j = c0 & 31;
        float4 w = *reinterpret_cast<const float4*>(&W_topo[slot * 1024 + k * 32 + j]);
        Wsm[k * 128 + p0]     = f2pack(w.x, w.y);
        Wsm[k * 128 + p0 + 1] = f2pack(w.z, w.w);
    }
    __syncthreads();

    int w  = tid >> 5;
    int wr = w >> 2, wc = w & 3;
    int lane = tid & 31;
    int ty = lane >> 3, tx = lane & 7;
    int rbase = wr * 32 + ty * 8;
    int pb    = wc * 32 + tx * 4;

    ull acc[8][4];
#pragma unroll
    for (int r = 0; r < 8; r++)
#pragma unroll
        for (int c = 0; c < 4; c++) acc[r][c] = 0ull;

#pragma unroll 4
    for (int k = 0; k < 32; k++) {
        const ulonglong2* Ap = reinterpret_cast<const ulonglong2*>(&Asm[k * 64 + rbase]);
        const ulonglong2* Wp = reinterpret_cast<const ulonglong2*>(&Wsm[k * 128 + pb]);
        ulonglong2 a01 = Ap[0], a23 = Ap[1], a45 = Ap[2], a67 = Ap[3];
        ulonglong2 w01 = Wp[0], w23 = Wp[1];
        ull a[8] = {a01.x, a01.y, a23.x, a23.y, a45.x, a45.y, a67.x, a67.y};
        ull wv[4] = {w01.x, w01.y, w23.x, w23.y};
#pragma unroll
        for (int r = 0; r < 8; r++)
#pragma unroll
            for (int c = 0; c < 4; c++)
                acc[r][c] = ffma2(a[r], wv[c], acc[r][c]);
    }

    int colg = colbase + wc * 64 + tx * 8;
#pragma unroll
    for (int r = 0; r < 8; r++) {
        int node = n0 + rbase + r;
        if (node >= N_PTOT) break;
        float l0, h0, l1, h1, l2, h2, l3, h3;
        f2unpack(acc[r][0], l0, h0);
        f2unpack(acc[r][1], l1, h1);
        f2unpack(acc[r][2], l2, h2);
        f2unpack(acc[r][3], l3, h3);
        uint4 o = make_uint4(h2u(l0, h0), h2u(l1, h1), h2u(l2, h2), h2u(l3, h3));
        *reinterpret_cast<uint4*>(&g_P[(size_t)node * 544 + colg]) = o;
    }
}

// ---------------------------------------------------------------------------
// K4: remaining dense jobs, pgemm-style 256-row x 64-col tiles, f32x2.
// Jobs: dual (node_feat @ [W_pins|W_pt]), B (net @ [b_topo|W_net]),
//       C (hanna @ [b_topo|W_connect]).
static constexpr int ND_DUAL = (N_CELL + 255) / 256;   // 196
static constexpr int ND_B    = (N_NET + 255) / 256;    // 40
static constexpr int ND_C    = (N_GCELL + 255) / 256;  // 79
static constexpr int NB_REST = ND_DUAL + ND_B + ND_C;  // 315
static constexpr int AR_STRIDE = 258;                  // ull stride per k (pad)
static constexpr int REST_SMEM = (32 * AR_STRIDE + 32 * 32) * 8;  // 74240 B

__global__ __launch_bounds__(256, 2) void dense_rest_kernel(
        const float* __restrict__ node_feat,
        const float* __restrict__ net_feat,
        const float* __restrict__ hanna_feat,
        const float* __restrict__ b_topo,
        const float* __restrict__ W_pins, const float* __restrict__ W_pt,
        const float* __restrict__ W_connect, const float* __restrict__ W_net,
        float* __restrict__ out_net) {
    extern __shared__ ull sm[];
    ull* Am = sm;                      // [k][row] (a,a) dup, stride 258
    ull* Wm = sm + 32 * AR_STRIDE;     // [k][pair 0..31]

    int bid = blockIdx.x;
    int tid = threadIdx.x;

    int jobtype, tile;
    if (bid < ND_DUAL)            { jobtype = 0; tile = bid; }
    else if (bid < ND_DUAL + ND_B){ jobtype = 1; tile = bid - ND_DUAL; }
    else                          { jobtype = 2; tile = bid - ND_DUAL - ND_B; }

    int n0 = tile * 256;
    int nrows = (jobtype == 0) ? N_CELL : (jobtype == 1) ? N_NET : N_GCELL;
    const float* X  = (jobtype == 0) ? node_feat : (jobtype == 1) ? net_feat : hanna_feat;
    const float* W1 = (jobtype == 0) ? W_pins : b_topo;
    const float* W2 = (jobtype == 0) ? W_pt : (jobtype == 1) ? W_net : W_connect;

    // ---- stage A: coalesced reads, k-major (a,a) duplicated ----
    for (int g = tid; g < 2048; g += 256) {       // 256 rows x 8 segs
        int row = g >> 3, seg = g & 7;
        int node = n0 + row;
        float4 x = make_float4(0.f, 0.f, 0.f, 0.f);
        if (node < nrows)
            x = *reinterpret_cast<const float4*>(&X[node * 32 + seg * 4]);
        Am[(seg * 4 + 0) * AR_STRIDE + row] = f2pack(x.x, x.x);
        Am[(seg * 4 + 1) * AR_STRIDE + row] = f2pack(x.y, x.y);
        Am[(seg * 4 + 2) * AR_STRIDE + row] = f2pack(x.z, x.z);
        Am[(seg * 4 + 3) * AR_STRIDE + row] = f2pack(x.w, x.w);
    }

    // ---- stage W: [W1 | W2] as 32 pairs per k ----
    for (int g = tid; g < 512; g += 256) {        // 32 k x 16 4-col granules
        int k = g >> 4, ph = g & 15;
        const float* src = (ph < 8) ? &W1[k * 32 + ph * 4] : &W2[k * 32 + (ph - 8) * 4];
        float4 wv = *reinterpret_cast<const float4*>(src);
        Wm[k * 32 + ph * 2]     = f2pack(wv.x, wv.y);
        Wm[k * 32 + ph * 2 + 1] = f2pack(wv.z, wv.w);
    }
    __syncthreads();

    int rg = tid >> 3;            // 0..31 -> 8 rows
    int pg = tid & 7;             // 0..7  -> 4 pairs (8 cols)
    int rbase = rg * 8;
    int pb = pg * 4;

    ull acc[8][4];
#pragma unroll
    for (int r = 0; r < 8; r++)
#pragma unroll
        for (int c = 0; c < 4; c++) acc[r][c] = 0ull;

#pragma unroll 4
    for (int k = 0; k < 32; k++) {
        const ulonglong2* Ap = reinterpret_cast<const ulonglong2*>(&Am[k * AR_STRIDE + rbase]);
        const ulonglong2* Wp = reinterpret_cast<const ulonglong2*>(&Wm[k * 32 + pb]);
        ulonglong2 a01 = Ap[0], a23 = Ap[1], a45 = Ap[2], a67 = Ap[3];
        ulonglong2 w01 = Wp[0], w23 = Wp[1];
        ull a[8] = {a01.x, a01.y, a23.x, a23.y, a45.x, a45.y, a67.x, a67.y};
        ull wv[4] = {w01.x, w01.y, w23.x, w23.y};
#pragma unroll
        for (int r = 0; r < 8; r++)
#pragma unroll
            for (int c = 0; c < 4; c++)
                acc[r][c] = ffma2(a[r], wv[c], acc[r][c]);
    }

    // ---- epilogue: pg<4 -> first 32 cols (W1 product), else W2 product ----
    bool first = (pg < 4);
    int c0 = (first ? pg : pg - 4) * 8;           // col base within 32-col half
#pragma unroll
    for (int r = 0; r < 8; r++) {
        int node = n0 + rbase + r;
        if (node >= nrows) break;
        float v0, v1, v2, v3, v4, v5, v6, v7;
        f2unpack(acc[r][0], v0, v1);
        f2unpack(acc[r][1], v2, v3);
        f2unpack(acc[r][2], v4, v5);
        f2unpack(acc[r][3], v6, v7);

        if (jobtype == 0) {
            float s; float* dst;
            if (first) { s = rsqrtf((float)max(g_deg[OFF_PINS_S + node], 1)); dst = &g_feat_pins[node * 32 + c0]; }
            else       { s = rsqrtf((float)max(g_deg[OFF_PT_S   + node], 1)); dst = &g_feat_pt[node * 32 + c0]; }
            *reinterpret_cast<float4*>(dst)     = make_float4(v0 * s, v1 * s, v2 * s, v3 * s);
            *reinterpret_cast<float4*>(dst + 4) = make_float4(v4 * s, v5 * s, v6 * s, v7 * s);
        } else if (first) {
            // b_topo product -> g_P bias slot (cols 512..543)
            int prow = (jobtype == 1) ? node : node + N_NET;
            uint4 o = make_uint4(h2u(v0, v1), h2u(v2, v3), h2u(v4, v5), h2u(v6, v7));
            *reinterpret_cast<uint4*>(&g_P[(size_t)prow * 544 + 512 + c0]) = o;
        } else if (jobtype == 1) {
            // net @ W_net -> accumulate onto bias-initialized out_net
            float4* o = reinterpret_cast<float4*>(&out_net[node * 32 + c0]);
            float4 a0 = o[0], a1 = o[1];
            o[0] = make_float4(a0.x + v0, a0.y + v1, a0.z + v2, a0.w + v3);
            o[1] = make_float4(a1.x + v4, a1.y + v5, a1.z + v6, a1.w + v7);
        } else {
            // hanna @ W_connect -> feat_connect (scaled)
            float s = rsqrtf((float)max(g_deg[OFF_CON_S + node], 1));
            float* dst = &g_feat_connect[node * 32 + c0];
            *reinterpret_cast<float4*>(dst)     = make_float4(v0 * s, v1 * s, v2 * s, v3 * s);
            *reinterpret_cast<float4*>(dst + 4) = make_float4(v4 * s, v5 * s, v6 * s, v7 * s);
        }
    }
}

// ---------------------------------------------------------------------------
// K5: all 5 edge relations, 4 edges/warp (8 lanes/edge) — R3/R7 proven form.
__global__ __launch_bounds__(256) void edge_kernel(
        const int* __restrict__ pins_src, const int* __restrict__ pins_dst,
        const int* __restrict__ con_src,  const int* __restrict__ con_dst,
        const int* __restrict__ pt_src,   const int* __restrict__ pt_dst,
        const int* __restrict__ pinned_src, const int* __restrict__ pinned_dst,
        const int* __restrict__ pf_src,   const int* __restrict__ pf_dst,
        const float* __restrict__ pin_feat, const float* __restrict__ edge_feat,
        float* __restrict__ out_cell, float* __restrict__ out_net, float* __restrict__ out_gcell) {
    int t = blockIdx.x * blockDim.x + threadIdx.x;
    int lane = t & 31;
    int e = ((t >> 5) << 2) + (lane >> 3);     // 4 edges per warp
    if (e >= E) return;
    int q = lane & 7;
    int baseLane = lane & 24;

    {
        int s = pins_src[e], d = pins_dst[e];
        float4 v = *reinterpret_cast<const float4*>(&g_feat_pins[s * 32 + q * 4]);
        float sc = rsqrtf((float)max(g_deg[OFF_PINS_D + d], 1));
        red_add_v4(out_net + d * 32 + q * 4, v.x * sc, v.y * sc, v.z * sc, v.w * sc);
    }
    {
        int s = con_src[e], d = con_dst[e];
        float4 v = *reinterpret_cast<const float4*>(&g_feat_connect[s * 32 + q * 4]);
        float sc = rsqrtf((float)max(g_deg[OFF_CON_D + d], 1));
        red_add_v4(out_gcell + d * 32 + q * 4, v.x * sc, v.y * sc, v.z * sc, v.w * sc);
    }
    {
        int s = pt_src[e], d = pt_dst[e];
        float4 v = *reinterpret_cast<const float4*>(&g_feat_pt[s * 32 + q * 4]);
        float sc = rsqrtf((float)max(g_deg[OFF_PT_D + d], 1));
        red_add_v4(out_gcell + d * 32 + q * 4, v.x * sc, v.y * sc, v.z * sc, v.w * sc);
    }

    {
        int sA = pinned_src[e], dA = pinned_dst[e];
        int sB = pf_src[e] + N_NET, dB = pf_dst[e];
        float evA0 = pin_feat[e * 16 + q],  evA1 = pin_feat[e * 16 + 8 + q];
        float evB0 = edge_feat[e * 16 + q], evB1 = edge_feat[e * 16 + 8 + q];

        const __half* PA = g_P + (size_t)sA * 544;
        const __half* PB = g_P + (size_t)sB * 544;

        float4 mA = ldh4(PA + 512 + q * 4);
        float4 mB = ldh4(PB + 512 + q * 4);

#pragma unroll
        for (int k = 0; k < 16; k++) {
            float cA = __shfl_sync(0xffffffffu, (k < 8) ? evA0 : evA1, baseLane + (k & 7));
            float cB = __shfl_sync(0xffffffffu, (k < 8) ? evB0 : evB1, baseLane + (k & 7));
            float4 pA = ldh4(PA + k * 32 + q * 4);
            float4 pB = ldh4(PB + k * 32 + q * 4);
            mA.x = fmaf(cA, pA.x, mA.x); mA.y = fmaf(cA, pA.y, mA.y);
            mA.z = fmaf(cA, pA.z, mA.z); mA.w = fmaf(cA, pA.w, mA.w);
            mB.x = fmaf(cB, pB.x, mB.x); mB.y = fmaf(cB, pB.y, mB.y);
            mB.z = fmaf(cB, pB.z, mB.z); mB.w = fmaf(cB, pB.w, mB.w);
        }

        float invA = 1.0f / (float)max(g_deg[OFF_PINNED_D + dA], 1);
        float invB = 1.0f / (float)max(g_deg[OFF_PF_D + dB], 1);
        red_add_v4(out_cell + dA * 32 + q * 4, mA.x * invA, mA.y * invA, mA.z * invA, mA.w * invA);
        red_add_v4(out_cell + dB * 32 + q * 4, mB.x * invB, mB.y * invB, mB.z * invB, mB.w * invB);
    }
}

// ---------------------------------------------------------------------------
extern "C" void kernel_launch(void* const* d_in, const int* in_sizes, int n_in,
                              void* d_out, int out_size) {
    const float* node_feat   = (const float*)d_in[0];
    const float* net_feat    = (const float*)d_in[1];
    const float* pin_feat    = (const float*)d_in[2];
    const float* hanna_feat  = (const float*)d_in[3];
    const float* edge_feat   = (const float*)d_in[4];
    const int*   pins_src    = (const int*)d_in[5];
    const int*   pins_dst    = (const int*)d_in[6];
    const int*   pinned_src  = (const int*)d_in[7];
    const int*   pinned_dst  = (const int*)d_in[8];
    const int*   connect_src = (const int*)d_in[9];
    const int*   connect_dst = (const int*)d_in[10];
    const int*   pt_src      = (const int*)d_in[11];
    const int*   pt_dst      = (const int*)d_in[12];
    const int*   pf_src      = (const int*)d_in[13];
    const int*   pf_dst      = (const int*)d_in[14];
    const float* W_net       = (const float*)d_in[15];
    const float* b_net       = (const float*)d_in[16];
    const float* W_topo      = (const float*)d_in[17];
    const float* b_topo      = (const float*)d_in[18];
    const float* W_pins      = (const float*)d_in[19];
    const float* b_pins      = (const float*)d_in[20];
    const float* W_connect   = (const float*)d_in[21];
    const float* b_connect   = (const float*)d_in[22];
    const float* W_pt        = (const float*)d_in[23];
    const float* b_pt        = (const float*)d_in[24];
    const float* b_pinned    = (const float*)d_in[25];
    const float* b_pf        = (const float*)d_in[26];

    float* out       = (float*)d_out;
    float* out_net   = out + (size_t)N_CELL * D;
    float* out_gcell = out + (size_t)(N_CELL + N_NET) * D;

    static bool attr_set = false;
    if (!attr_set) {
        cudaFuncSetAttribute(dense_rest_kernel,
                             cudaFuncAttributeMaxDynamicSharedMemorySize, REST_SMEM);
        attr_set = true;
    }

    // K1: fused init (zero degrees + bias-sum output init), vectorized
    init_fused_kernel<<<(INIT_V4 + 255) / 256, 256>>>(out, b_pinned, b_pf, b_pins, b_net,
                                                      b_connect, b_pt);

    // K2: degrees
    degree_kernel<<<(E + 255) / 256, 256>>>(pins_src, pins_dst, connect_src, connect_dst,
                                            pt_src, pt_dst, pinned_dst, pf_dst);

    // K3: P-GEMM slots 0..15
    pgemm_kernel<<<PG_BLOCKS, 256>>>(net_feat, hanna_feat, W_topo);

    // K4: remaining dense jobs, pgemm-style tiles
    dense_rest_kernel<<<NB_REST, 256, REST_SMEM>>>(node_feat, net_feat, hanna_feat,
                                                   b_topo, W_pins, W_pt, W_connect, W_net,
                                                   out_net);

    // K5: all 5 edge relations (proven kernel)
    const int EGRID = (E / 4 * 32 + 255) / 256;   // 3125 blocks
    edge_kernel<<<EGRID, 256>>>(pins_src, pins_dst, connect_src, connect_dst,
                                pt_src, pt_dst, pinned_src, pinned_dst, pf_src, pf_dst,
                                pin_feat, edge_feat, out, out_net, out_gcell);
}